// round 1
// baseline (speedup 1.0000x reference)
#include <cuda_runtime.h>
#include <cuda_bf16.h>

#define NN 50000
#define EE 400000
#define CD 128
#define NEG_BIG (-3.402823466e38f)

// ---------------- device scratch (static, no allocations) ----------------
// 16 feature buffers of [NN, CD] floats:
// 0:Kf_u 1:Kf_i 2:Q_i 3:Q_u 4:Vm_u 5:Vm_i 6:Vraw_u 7:Vraw_i
// 8:LT_u 9:HT_u 10:LT_i 11:HT_i 12:HZ0 13:HZ1 14:XP 15:T
__device__ float g_bufs[16][NN * CD];
__device__ float g_rawbuf[(size_t)EE * 8];
__device__ int   g_cnt[2][NN];
__device__ int   g_cur[2][NN];
__device__ int   g_off[2][NN + 1];
__device__ int   g_eidx[2][EE];
__device__ float g_Wfold[4][CD * CD];
__device__ float g_bfold[4][CD];

// ---------------- small kernels ----------------
__global__ void zero_kernel() {
    int i = blockIdx.x * blockDim.x + threadIdx.x;
    if (i < 2 * NN) {
        (&g_cnt[0][0])[i] = 0;
        (&g_cur[0][0])[i] = 0;
    }
}

// Fold relation transforms into linear weights:
// W'[i][h*16+k] = sum_j W[i][h*16+j] * R[h][j][k] ;  b' likewise.
__global__ void fold_kernel(const float* __restrict__ Wk_u, const float* __restrict__ bk_u,
                            const float* __restrict__ Wk_i, const float* __restrict__ bk_i,
                            const float* __restrict__ Wv_u, const float* __restrict__ bv_u,
                            const float* __restrict__ Wv_i, const float* __restrict__ bv_i,
                            const float* __restrict__ rel_att, const float* __restrict__ rel_msg) {
    int idx = blockIdx.x * blockDim.x + threadIdx.x;
    if (idx >= 4 * CD * CD) return;
    int f = idx >> 14;          // which fold
    int r = idx & 16383;
    int i = r >> 7;             // input row
    int c = r & 127;            // output col
    int h = c >> 4, kk = c & 15;
    const float* W; const float* b; const float* R;
    if (f == 0)      { W = Wk_u; b = bk_u; R = rel_att; }
    else if (f == 1) { W = Wk_i; b = bk_i; R = rel_att + 2048; }
    else if (f == 2) { W = Wv_u; b = bv_u; R = rel_msg; }
    else             { W = Wv_i; b = bv_i; R = rel_msg + 2048; }
    float s = 0.f;
    #pragma unroll
    for (int j = 0; j < 16; ++j)
        s += W[i * CD + h * 16 + j] * R[h * 256 + j * 16 + kk];
    g_Wfold[f][i * CD + c] = s;
    if (i == 0) {
        float sb = 0.f;
        #pragma unroll
        for (int j = 0; j < 16; ++j)
            sb += b[h * 16 + j] * R[h * 256 + j * 16 + kk];
        g_bfold[f][c] = sb;
    }
}

__global__ void count_kernel(const int* __restrict__ bd, const int* __restrict__ rd) {
    int i = blockIdx.x * blockDim.x + threadIdx.x;
    if (i >= 2 * EE) return;
    if (i < EE) atomicAdd(&g_cnt[0][bd[i]], 1);
    else        atomicAdd(&g_cnt[1][rd[i - EE]], 1);
}

__global__ void scan_kernel() {   // grid = 2 blocks, 1024 threads
    int rel = blockIdx.x;
    __shared__ int partial[1024];
    const int CH = (NN + 1023) / 1024;
    int t = threadIdx.x;
    int begin = t * CH;
    int end   = begin + CH < NN ? begin + CH : NN;
    if (begin > NN) begin = NN;
    if (end < begin) end = begin;
    int s = 0;
    for (int i = begin; i < end; ++i) s += g_cnt[rel][i];
    partial[t] = s;
    __syncthreads();
    for (int off = 1; off < 1024; off <<= 1) {
        int v = (t >= off) ? partial[t - off] : 0;
        __syncthreads();
        partial[t] += v;
        __syncthreads();
    }
    int run = partial[t] - s;   // exclusive prefix of this chunk
    for (int i = begin; i < end; ++i) {
        g_off[rel][i] = run;
        run += g_cnt[rel][i];
    }
    if (t == 1023) g_off[rel][NN] = partial[1023];
}

__global__ void scatter_kernel(const int* __restrict__ bd, const int* __restrict__ rd) {
    int i = blockIdx.x * blockDim.x + threadIdx.x;
    if (i >= 2 * EE) return;
    int rel = i < EE ? 0 : 1;
    int e   = i < EE ? i : i - EE;
    int dst = rel ? rd[e] : bd[e];
    int pos = atomicAdd(&g_cur[rel][dst], 1);
    g_eidx[rel][g_off[rel][dst] + pos] = e;
}

// ---------------- GEMM: C = act(A[n,128] @ W[128,128] + bias) ----------------
// mode 0: none; mode 1: tanh; mode 2: residual blend  out = x*a + resid*(1-a), a=sigmoid(*skipP)
__global__ __launch_bounds__(256, 2) void gemm128(
    const float* __restrict__ A, const float* __restrict__ W,
    const float* __restrict__ bias, float* __restrict__ C,
    int n, int mode, const float* __restrict__ resid, const float* __restrict__ skipP) {
    __shared__ float As[128][33];
    __shared__ float Ws[32][128];
    int tid = threadIdx.x;
    int tx = tid & 15, ty = tid >> 4;
    int m0 = blockIdx.x * 128;

    float acc[8][8];
    #pragma unroll
    for (int i = 0; i < 8; ++i)
        #pragma unroll
        for (int j = 0; j < 8; ++j) acc[i][j] = 0.f;

    for (int kc = 0; kc < 4; ++kc) {
        #pragma unroll
        for (int l = 0; l < 4; ++l) {          // A chunk: 128 rows x 32 k
            int lin = tid + l * 256;
            int row = lin >> 3, kq = lin & 7;
            float4 a4 = make_float4(0.f, 0.f, 0.f, 0.f);
            if (m0 + row < n)
                a4 = *reinterpret_cast<const float4*>(A + (size_t)(m0 + row) * CD + kc * 32 + kq * 4);
            As[row][kq * 4 + 0] = a4.x;
            As[row][kq * 4 + 1] = a4.y;
            As[row][kq * 4 + 2] = a4.z;
            As[row][kq * 4 + 3] = a4.w;
        }
        #pragma unroll
        for (int l = 0; l < 4; ++l) {          // W chunk: 32 k x 128 n
            int lin = tid + l * 256;
            int kr = lin >> 5, c4 = lin & 31;
            *reinterpret_cast<float4*>(&Ws[kr][c4 * 4]) =
                *reinterpret_cast<const float4*>(W + (size_t)(kc * 32 + kr) * CD + c4 * 4);
        }
        __syncthreads();
        #pragma unroll
        for (int k = 0; k < 32; ++k) {
            float a[8], b[8];
            #pragma unroll
            for (int i = 0; i < 8; ++i) a[i] = As[ty + 16 * i][k];
            #pragma unroll
            for (int j = 0; j < 8; ++j) b[j] = Ws[k][tx + 16 * j];
            #pragma unroll
            for (int i = 0; i < 8; ++i)
                #pragma unroll
                for (int j = 0; j < 8; ++j) acc[i][j] += a[i] * b[j];
        }
        __syncthreads();
    }

    float alpha = 0.f, beta = 0.f;
    if (mode == 2) {
        alpha = 1.f / (1.f + __expf(-skipP[0]));
        beta = 1.f - alpha;
    }
    #pragma unroll
    for (int i = 0; i < 8; ++i) {
        int row = m0 + ty + 16 * i;
        if (row < n) {
            #pragma unroll
            for (int j = 0; j < 8; ++j) {
                int col = tx + 16 * j;
                float x = acc[i][j] + bias[col];
                if (mode == 1) x = tanhf(x);
                else if (mode == 2) x = x * alpha + resid[(size_t)row * CD + col] * beta;
                C[(size_t)row * CD + col] = x;
            }
        }
    }
}

// ---------------- edge attention + aggregation: one warp per destination ----------------
__global__ void edge_kernel(const float* __restrict__ q, const float* __restrict__ kf,
                            const float* __restrict__ v, const float* __restrict__ vraw,
                            const int* __restrict__ src, const float* __restrict__ rp,
                            int rel, float* __restrict__ lt, float* __restrict__ ht) {
    int w = (blockIdx.x * blockDim.x + threadIdx.x) >> 5;
    int lane = threadIdx.x & 31;
    if (w >= NN) return;
    int head = lane >> 2;
    const int* eix = g_eidx[rel];
    int o0 = g_off[rel][w], o1 = g_off[rel][w + 1];

    float4 q4 = *reinterpret_cast<const float4*>(q + (size_t)w * CD + lane * 4);
    float sc = rp[head] * 0.25f;            // rel_pri[h] / sqrt(DK)
    q4.x *= sc; q4.y *= sc; q4.z *= sc; q4.w *= sc;

    float m_l = NEG_BIG, m_h = NEG_BIG, z_l = 0.f, z_h = 0.f;
    for (int e = o0; e < o1; ++e) {
        int s = src[eix[e]];
        float4 k4 = *reinterpret_cast<const float4*>(kf + (size_t)s * CD + lane * 4);
        float p = q4.x * k4.x + q4.y * k4.y + q4.z * k4.z + q4.w * k4.w;
        p += __shfl_xor_sync(0xffffffffu, p, 1);
        p += __shfl_xor_sync(0xffffffffu, p, 2);
        // p == raw logit for this lane's head (identical across 4-lane group)
        float iv = 1.f / (p + 1e-6f);
        float mn = fmaxf(m_l, p);
        z_l = z_l * __expf(m_l - mn) + __expf(p - mn);
        m_l = mn;
        mn = fmaxf(m_h, iv);
        z_h = z_h * __expf(m_h - mn) + __expf(iv - mn);
        m_h = mn;
        if ((lane & 3) == 0) g_rawbuf[(size_t)e * 8 + head] = p;
    }
    __threadfence_block();
    __syncwarp();

    float izl = z_l > 0.f ? 1.f / z_l : 0.f;
    float izh = z_h > 0.f ? 1.f / z_h : 0.f;
    float4 al = make_float4(0.f, 0.f, 0.f, 0.f);
    float4 ah = make_float4(0.f, 0.f, 0.f, 0.f);
    for (int e = o0; e < o1; ++e) {
        int s = src[eix[e]];
        float raw = g_rawbuf[(size_t)e * 8 + head];
        float wl = __expf(raw - m_l) * izl;
        float wh = __expf(1.f / (raw + 1e-6f) - m_h) * izh;
        float4 v4 = *reinterpret_cast<const float4*>(v + (size_t)s * CD + lane * 4);
        al.x += v4.x * wl; al.y += v4.y * wl; al.z += v4.z * wl; al.w += v4.w * wl;
        ah.x += v4.x * wh; ah.y += v4.y * wh; ah.z += v4.z * wh; ah.w += v4.w * wh;
    }
    float4 o = *reinterpret_cast<const float4*>(vraw + (size_t)w * CD + lane * 4);
    float4 lo = make_float4(o.x + al.x, o.y + al.y, o.z + al.z, o.w + al.w);
    float4 ho = make_float4(o.x - ah.x, o.y - ah.y, o.z - ah.z, o.w - ah.w);
    *reinterpret_cast<float4*>(lt + (size_t)w * CD + lane * 4) = lo;
    *reinterpret_cast<float4*>(ht + (size_t)w * CD + lane * 4) = ho;
}

// ---------------- gating: sc = softmax_k(dot(hz_k, xp)); T = lt*sc0 + ht*sc1 ----------------
__global__ void gate_kernel(const float* __restrict__ hz0, const float* __restrict__ hz1,
                            const float* __restrict__ xp, const float* __restrict__ ltb,
                            const float* __restrict__ htb, float* __restrict__ T) {
    int w = (blockIdx.x * blockDim.x + threadIdx.x) >> 5;
    int lane = threadIdx.x & 31;
    if (w >= NN) return;
    size_t base = (size_t)w * CD + lane * 4;
    float4 x  = *reinterpret_cast<const float4*>(xp + base);
    float4 h0 = *reinterpret_cast<const float4*>(hz0 + base);
    float4 h1 = *reinterpret_cast<const float4*>(hz1 + base);
    float s0 = h0.x * x.x + h0.y * x.y + h0.z * x.z + h0.w * x.w;
    float s1 = h1.x * x.x + h1.y * x.y + h1.z * x.z + h1.w * x.w;
    #pragma unroll
    for (int off = 16; off > 0; off >>= 1) {
        s0 += __shfl_xor_sync(0xffffffffu, s0, off);
        s1 += __shfl_xor_sync(0xffffffffu, s1, off);
    }
    float mx = fmaxf(s0, s1);
    float e0 = __expf(s0 - mx), e1 = __expf(s1 - mx);
    float r = 1.f / (e0 + e1);
    float c0 = e0 * r, c1 = e1 * r;
    float4 l = *reinterpret_cast<const float4*>(ltb + base);
    float4 h = *reinterpret_cast<const float4*>(htb + base);
    *reinterpret_cast<float4*>(T + base) =
        make_float4(l.x * c0 + h.x * c1, l.y * c0 + h.y * c1,
                    l.z * c0 + h.z * c1, l.w * c0 + h.w * c1);
}

// ---------------- host launcher ----------------
extern "C" void kernel_launch(void* const* d_in, const int* in_sizes, int n_in,
                              void* d_out, int out_size) {
    const float* h_user  = (const float*)d_in[0];
    const float* h_item  = (const float*)d_in[1];
    const int* buys_src  = (const int*)d_in[2];
    const int* buys_dst  = (const int*)d_in[3];
    const int* rev_src   = (const int*)d_in[4];
    const int* rev_dst   = (const int*)d_in[5];
    const float* Wk_u = (const float*)d_in[6];   const float* bk_u = (const float*)d_in[7];
    const float* Wk_i = (const float*)d_in[8];   const float* bk_i = (const float*)d_in[9];
    const float* Wq_u = (const float*)d_in[10];  const float* bq_u = (const float*)d_in[11];
    const float* Wq_i = (const float*)d_in[12];  const float* bq_i = (const float*)d_in[13];
    const float* Wv_u = (const float*)d_in[14];  const float* bv_u = (const float*)d_in[15];
    const float* Wv_i = (const float*)d_in[16];  const float* bv_i = (const float*)d_in[17];
    const float* Wa_u = (const float*)d_in[18];  const float* ba_u = (const float*)d_in[19];
    const float* Wa_i = (const float*)d_in[20];  const float* ba_i = (const float*)d_in[21];
    const float* Wf_  = (const float*)d_in[22];  const float* bf_  = (const float*)d_in[23];
    const float* Wx_  = (const float*)d_in[24];  const float* bx_  = (const float*)d_in[25];
    const float* rel_pri = (const float*)d_in[26];
    const float* rel_att = (const float*)d_in[27];
    const float* rel_msg = (const float*)d_in[28];
    const float* skip    = (const float*)d_in[29];
    (void)in_sizes; (void)n_in; (void)out_size;

    float* buf;    cudaGetSymbolAddress((void**)&buf, g_bufs);
    float* wfold;  cudaGetSymbolAddress((void**)&wfold, g_Wfold);
    float* bfold;  cudaGetSymbolAddress((void**)&bfold, g_bfold);
    auto B = [&](int i) { return buf + (size_t)i * NN * CD; };

    zero_kernel<<<(2 * NN + 255) / 256, 256>>>();
    fold_kernel<<<(4 * CD * CD + 255) / 256, 256>>>(Wk_u, bk_u, Wk_i, bk_i,
                                                    Wv_u, bv_u, Wv_i, bv_i,
                                                    rel_att, rel_msg);
    count_kernel<<<(2 * EE + 255) / 256, 256>>>(buys_dst, rev_dst);
    scan_kernel<<<2, 1024>>>();
    scatter_kernel<<<(2 * EE + 255) / 256, 256>>>(buys_dst, rev_dst);

    dim3 gg((NN + 127) / 128);
    // feature GEMMs
    gemm128<<<gg, 256>>>(h_user, wfold + 0 * CD * CD, bfold + 0 * CD, B(0), NN, 0, nullptr, nullptr); // Kf_u
    gemm128<<<gg, 256>>>(h_item, wfold + 1 * CD * CD, bfold + 1 * CD, B(1), NN, 0, nullptr, nullptr); // Kf_i
    gemm128<<<gg, 256>>>(h_item, Wq_i, bq_i, B(2), NN, 0, nullptr, nullptr);                          // Q_i
    gemm128<<<gg, 256>>>(h_user, Wq_u, bq_u, B(3), NN, 0, nullptr, nullptr);                          // Q_u
    gemm128<<<gg, 256>>>(h_user, wfold + 2 * CD * CD, bfold + 2 * CD, B(4), NN, 0, nullptr, nullptr); // Vm_u
    gemm128<<<gg, 256>>>(h_item, wfold + 3 * CD * CD, bfold + 3 * CD, B(5), NN, 0, nullptr, nullptr); // Vm_i
    gemm128<<<gg, 256>>>(h_user, Wv_u, bv_u, B(6), NN, 0, nullptr, nullptr);                          // Vraw_u
    gemm128<<<gg, 256>>>(h_item, Wv_i, bv_i, B(7), NN, 0, nullptr, nullptr);                          // Vraw_i

    int wb = (NN * 32 + 255) / 256;
    // rel0: user -> item  (writes LT_i/HT_i)
    edge_kernel<<<wb, 256>>>(B(2), B(0), B(4), B(7), buys_src, rel_pri + 0, 0, B(10), B(11));
    // rel1: item -> user  (writes LT_u/HT_u)
    edge_kernel<<<wb, 256>>>(B(3), B(1), B(5), B(6), rev_src, rel_pri + 8, 1, B(8), B(9));

    float* out = (float*)d_out;
    for (int t = 0; t < 2; ++t) {
        const float* LT = (t == 0) ? B(8)  : B(10);
        const float* HT = (t == 0) ? B(9)  : B(11);
        const float* VR = (t == 0) ? B(6)  : B(7);
        const float* hn = (t == 0) ? h_user : h_item;
        const float* Wa = (t == 0) ? Wa_u : Wa_i;
        const float* ba = (t == 0) ? ba_u : ba_i;
        gemm128<<<gg, 256>>>(LT, Wf_, bf_, B(12), NN, 1, nullptr, nullptr); // HZ0 = tanh(LT@Wf+bf)
        gemm128<<<gg, 256>>>(HT, Wf_, bf_, B(13), NN, 1, nullptr, nullptr); // HZ1 = tanh(HT@Wf+bf)
        gemm128<<<gg, 256>>>(VR, Wx_, bx_, B(14), NN, 1, nullptr, nullptr); // XP  = tanh(ori@Wx+bx)
        gate_kernel<<<wb, 256>>>(B(12), B(13), B(14), LT, HT, B(15));       // T
        gemm128<<<gg, 256>>>(B(15), Wa, ba, out + (size_t)t * NN * CD, NN, 2, hn, skip + t);
    }
}

// round 6
// speedup vs baseline: 1.1111x; 1.1111x over previous
#include <cuda_runtime.h>
#include <cuda_bf16.h>

#define NN 50000
#define EE 400000
#define CD 128
#define NEG_BIG (-3.402823466e38f)
#define SCAN_B 512
#define SCAN_NB ((NN + SCAN_B - 1) / SCAN_B)

// ---------------- device scratch (static, no allocations) ----------------
// 16 feature buffers of [NN, CD] floats:
// 0:Kf_u 1:Kf_i 2:Q_i 3:Q_u 4:Vm_u 5:Vm_i 6:Vraw_u 7:Vraw_i
// 8:LT_u 9:HT_u 10:LT_i 11:HT_i 12:HZ0 13:HZ1 14:XP 15:T
__device__ float g_bufs[16][NN * CD];
__device__ float g_rawbuf[(size_t)EE * 8];
__device__ int   g_cnt[2][NN];
__device__ int   g_cur[2][NN];
__device__ int   g_off[2][NN + 1];
__device__ int   g_eidx[2][EE];
__device__ int   g_bsum[2][SCAN_NB];
__device__ float g_Wfold[4][CD * CD];
__device__ float g_bfold[4][CD];
// bf16 hi/lo split weights: 0-3 folded(Ku,Ki,Vmu,Vmi), 4:Wq_u 5:Wq_i 6:Wv_u 7:Wv_i 8:Wf 9:Wx 10:Wa_u 11:Wa_i
__device__ __nv_bfloat16 g_wh[12][CD * CD];
__device__ __nv_bfloat16 g_wl[12][CD * CD];

// ---------------- small kernels ----------------
__global__ void zero_kernel() {
    int i = blockIdx.x * blockDim.x + threadIdx.x;
    if (i < 2 * NN) {
        (&g_cnt[0][0])[i] = 0;
        (&g_cur[0][0])[i] = 0;
    }
}

// Fold relation transforms into linear weights:
// W'[i][h*16+k] = sum_j W[i][h*16+j] * R[h][j][k] ;  b' likewise.
__global__ void fold_kernel(const float* __restrict__ Wk_u, const float* __restrict__ bk_u,
                            const float* __restrict__ Wk_i, const float* __restrict__ bk_i,
                            const float* __restrict__ Wv_u, const float* __restrict__ bv_u,
                            const float* __restrict__ Wv_i, const float* __restrict__ bv_i,
                            const float* __restrict__ rel_att, const float* __restrict__ rel_msg) {
    int idx = blockIdx.x * blockDim.x + threadIdx.x;
    if (idx >= 4 * CD * CD) return;
    int f = idx >> 14;
    int r = idx & 16383;
    int i = r >> 7;
    int c = r & 127;
    int h = c >> 4, kk = c & 15;
    const float* W; const float* b; const float* R;
    if (f == 0)      { W = Wk_u; b = bk_u; R = rel_att; }
    else if (f == 1) { W = Wk_i; b = bk_i; R = rel_att + 2048; }
    else if (f == 2) { W = Wv_u; b = bv_u; R = rel_msg; }
    else             { W = Wv_i; b = bv_i; R = rel_msg + 2048; }
    float s = 0.f;
    #pragma unroll
    for (int j = 0; j < 16; ++j)
        s += W[i * CD + h * 16 + j] * R[h * 256 + j * 16 + kk];
    g_Wfold[f][i * CD + c] = s;
    if (i == 0) {
        float sb = 0.f;
        #pragma unroll
        for (int j = 0; j < 16; ++j)
            sb += b[h * 16 + j] * R[h * 256 + j * 16 + kk];
        g_bfold[f][c] = sb;
    }
}

// Convert weight matrices to bf16 hi/lo splits (slots 2,3,6..11 used).
__global__ void wprep_kernel(const float* __restrict__ Wq_u, const float* __restrict__ Wq_i,
                             const float* __restrict__ Wv_u, const float* __restrict__ Wv_i,
                             const float* __restrict__ Wf, const float* __restrict__ Wx,
                             const float* __restrict__ Wa_u, const float* __restrict__ Wa_i) {
    int idx = blockIdx.x * blockDim.x + threadIdx.x;
    if (idx >= 12 * CD * CD) return;
    int w = idx >> 14, r = idx & 16383;
    float x;
    switch (w) {
        case 0: x = g_Wfold[0][r]; break;
        case 1: x = g_Wfold[1][r]; break;
        case 2: x = g_Wfold[2][r]; break;
        case 3: x = g_Wfold[3][r]; break;
        case 4: x = Wq_u[r]; break;
        case 5: x = Wq_i[r]; break;
        case 6: x = Wv_u[r]; break;
        case 7: x = Wv_i[r]; break;
        case 8: x = Wf[r]; break;
        case 9: x = Wx[r]; break;
        case 10: x = Wa_u[r]; break;
        default: x = Wa_i[r]; break;
    }
    __nv_bfloat16 h = __float2bfloat16(x);
    g_wh[w][r] = h;
    g_wl[w][r] = __float2bfloat16(x - __bfloat162float(h));
}

__global__ void count_kernel(const int* __restrict__ bd, const int* __restrict__ rd) {
    int i = blockIdx.x * blockDim.x + threadIdx.x;
    if (i >= 2 * EE) return;
    if (i < EE) atomicAdd(&g_cnt[0][bd[i]], 1);
    else        atomicAdd(&g_cnt[1][rd[i - EE]], 1);
}

// --- 3-phase scan ---
__global__ void scan_a() {
    int rel = blockIdx.y;
    int i = blockIdx.x * SCAN_B + threadIdx.x;
    __shared__ int sh[SCAN_B];
    int v = (i < NN) ? g_cnt[rel][i] : 0;
    sh[threadIdx.x] = v;
    __syncthreads();
    for (int off = 1; off < SCAN_B; off <<= 1) {
        int t = (threadIdx.x >= off) ? sh[threadIdx.x - off] : 0;
        __syncthreads();
        sh[threadIdx.x] += t;
        __syncthreads();
    }
    if (i < NN) g_off[rel][i] = sh[threadIdx.x] - v;
    if (threadIdx.x == SCAN_B - 1) g_bsum[rel][blockIdx.x] = sh[SCAN_B - 1];
}

__global__ void scan_b() {
    int rel = threadIdx.x >> 5;
    int lane = threadIdx.x & 31;
    if (rel >= 2) return;
    int base = lane * 4;
    int v[4];
    int tot = 0;
    #pragma unroll
    for (int j = 0; j < 4; ++j) {
        v[j] = (base + j < SCAN_NB) ? g_bsum[rel][base + j] : 0;
        tot += v[j];
    }
    int inc = tot;
    #pragma unroll
    for (int off = 1; off < 32; off <<= 1) {
        int t = __shfl_up_sync(0xffffffffu, inc, off);
        if (lane >= off) inc += t;
    }
    int run = inc - tot;
    #pragma unroll
    for (int j = 0; j < 4; ++j) {
        if (base + j < SCAN_NB) g_bsum[rel][base + j] = run;
        run += v[j];
    }
    if (lane == 31) g_off[rel][NN] = inc;
}

__global__ void scan_c() {
    int rel = blockIdx.y;
    int i = blockIdx.x * SCAN_B + threadIdx.x;
    if (i < NN) g_off[rel][i] += g_bsum[rel][blockIdx.x];
}

__global__ void scatter_kernel(const int* __restrict__ bd, const int* __restrict__ rd) {
    int i = blockIdx.x * blockDim.x + threadIdx.x;
    if (i >= 2 * EE) return;
    int rel = i < EE ? 0 : 1;
    int e   = i < EE ? i : i - EE;
    int dst = rel ? rd[e] : bd[e];
    int pos = atomicAdd(&g_cur[rel][dst], 1);
    g_eidx[rel][g_off[rel][dst] + pos] = e;
}

// ---------------- fp32 SIMT GEMM (precision-critical Q/K path) ----------------
__global__ __launch_bounds__(256, 2) void gemm128_f32(
    const float* __restrict__ A, const float* __restrict__ W,
    const float* __restrict__ bias, float* __restrict__ C, int n) {
    __shared__ float As[128][33];
    __shared__ float Ws[32][128];
    int tid = threadIdx.x;
    int tx = tid & 15, ty = tid >> 4;
    int m0 = blockIdx.x * 128;

    float acc[8][8];
    #pragma unroll
    for (int i = 0; i < 8; ++i)
        #pragma unroll
        for (int j = 0; j < 8; ++j) acc[i][j] = 0.f;

    for (int kc = 0; kc < 4; ++kc) {
        #pragma unroll
        for (int l = 0; l < 4; ++l) {
            int lin = tid + l * 256;
            int row = lin >> 3, kq = lin & 7;
            float4 a4 = make_float4(0.f, 0.f, 0.f, 0.f);
            if (m0 + row < n)
                a4 = *reinterpret_cast<const float4*>(A + (size_t)(m0 + row) * CD + kc * 32 + kq * 4);
            As[row][kq * 4 + 0] = a4.x;
            As[row][kq * 4 + 1] = a4.y;
            As[row][kq * 4 + 2] = a4.z;
            As[row][kq * 4 + 3] = a4.w;
        }
        #pragma unroll
        for (int l = 0; l < 4; ++l) {
            int lin = tid + l * 256;
            int kr = lin >> 5, c4 = lin & 31;
            *reinterpret_cast<float4*>(&Ws[kr][c4 * 4]) =
                *reinterpret_cast<const float4*>(W + (size_t)(kc * 32 + kr) * CD + c4 * 4);
        }
        __syncthreads();
        #pragma unroll
        for (int k = 0; k < 32; ++k) {
            float a[8], b[8];
            #pragma unroll
            for (int i = 0; i < 8; ++i) a[i] = As[ty + 16 * i][k];
            #pragma unroll
            for (int j = 0; j < 8; ++j) b[j] = Ws[k][tx + 16 * j];
            #pragma unroll
            for (int i = 0; i < 8; ++i)
                #pragma unroll
                for (int j = 0; j < 8; ++j) acc[i][j] += a[i] * b[j];
        }
        __syncthreads();
    }

    #pragma unroll
    for (int i = 0; i < 8; ++i) {
        int row = m0 + ty + 16 * i;
        if (row < n) {
            #pragma unroll
            for (int j = 0; j < 8; ++j) {
                int col = tx + 16 * j;
                C[(size_t)row * CD + col] = acc[i][j] + bias[col];
            }
        }
    }
}

// ---------------- bf16x3 tensor-core GEMM ----------------
#define BK 32

__device__ __forceinline__ void mma_bf16(float* c, const unsigned* a, const unsigned* b) {
    asm volatile("mma.sync.aligned.m16n8k16.row.col.f32.bf16.bf16.f32 "
        "{%0,%1,%2,%3}, {%4,%5,%6,%7}, {%8,%9}, {%0,%1,%2,%3};"
        : "+f"(c[0]), "+f"(c[1]), "+f"(c[2]), "+f"(c[3])
        : "r"(a[0]), "r"(a[1]), "r"(a[2]), "r"(a[3]), "r"(b[0]), "r"(b[1]));
}

__global__ __launch_bounds__(256, 2) void gemm128_tc(
    const float* __restrict__ A, const __nv_bfloat16* __restrict__ Wh,
    const __nv_bfloat16* __restrict__ Wl, const float* __restrict__ bias,
    float* __restrict__ C, int n, int mode,
    const float* __restrict__ resid, const float* __restrict__ skipP) {
    __shared__ __nv_bfloat16 Ah[128][BK + 2];
    __shared__ __nv_bfloat16 Al[128][BK + 2];
    __shared__ __nv_bfloat16 Bh[128][BK + 2];
    __shared__ __nv_bfloat16 Bl[128][BK + 2];

    int tid = threadIdx.x;
    int lane = tid & 31;
    int wid = tid >> 5;
    int wm = wid & 3;
    int wn = wid >> 2;
    int m0 = blockIdx.x * 128;

    float c[2][8][4];
    #pragma unroll
    for (int i = 0; i < 2; ++i)
        #pragma unroll
        for (int j = 0; j < 8; ++j)
            #pragma unroll
            for (int q = 0; q < 4; ++q) c[i][j][q] = 0.f;

    for (int kc = 0; kc < 4; ++kc) {
        #pragma unroll
        for (int l = 0; l < 4; ++l) {
            int lin = tid + l * 256;
            int row = lin >> 3, quad = lin & 7;
            float4 a4 = make_float4(0.f, 0.f, 0.f, 0.f);
            if (m0 + row < n)
                a4 = *reinterpret_cast<const float4*>(A + (size_t)(m0 + row) * CD + kc * 32 + quad * 4);
            int cb = quad * 4;
            float xs[4] = {a4.x, a4.y, a4.z, a4.w};
            #pragma unroll
            for (int q = 0; q < 4; ++q) {
                __nv_bfloat16 h = __float2bfloat16(xs[q]);
                Ah[row][cb + q] = h;
                Al[row][cb + q] = __float2bfloat16(xs[q] - __bfloat162float(h));
            }
        }
        #pragma unroll
        for (int l = 0; l < 16; ++l) {
            int lin = tid + l * 256;
            int kr = lin >> 7, nn = lin & 127;
            Bh[nn][kr] = Wh[(size_t)(kc * 32 + kr) * CD + nn];
            Bl[nn][kr] = Wl[(size_t)(kc * 32 + kr) * CD + nn];
        }
        __syncthreads();

        #pragma unroll
        for (int ks = 0; ks < 2; ++ks) {
            int kb = ks * 16;
            int r = lane >> 2, cq = (lane & 3) * 2;
            unsigned afh[2][4], afl[2][4];
            #pragma unroll
            for (int mt = 0; mt < 2; ++mt) {
                int row = wm * 32 + mt * 16 + r;
                afh[mt][0] = *reinterpret_cast<const unsigned*>(&Ah[row][kb + cq]);
                afh[mt][1] = *reinterpret_cast<const unsigned*>(&Ah[row + 8][kb + cq]);
                afh[mt][2] = *reinterpret_cast<const unsigned*>(&Ah[row][kb + cq + 8]);
                afh[mt][3] = *reinterpret_cast<const unsigned*>(&Ah[row + 8][kb + cq + 8]);
                afl[mt][0] = *reinterpret_cast<const unsigned*>(&Al[row][kb + cq]);
                afl[mt][1] = *reinterpret_cast<const unsigned*>(&Al[row + 8][kb + cq]);
                afl[mt][2] = *reinterpret_cast<const unsigned*>(&Al[row][kb + cq + 8]);
                afl[mt][3] = *reinterpret_cast<const unsigned*>(&Al[row + 8][kb + cq + 8]);
            }
            #pragma unroll
            for (int nt = 0; nt < 8; ++nt) {
                int col = wn * 64 + nt * 8 + (lane >> 2);
                unsigned bfh[2], bfl[2];
                bfh[0] = *reinterpret_cast<const unsigned*>(&Bh[col][kb + cq]);
                bfh[1] = *reinterpret_cast<const unsigned*>(&Bh[col][kb + cq + 8]);
                bfl[0] = *reinterpret_cast<const unsigned*>(&Bl[col][kb + cq]);
                bfl[1] = *reinterpret_cast<const unsigned*>(&Bl[col][kb + cq + 8]);
                #pragma unroll
                for (int mt = 0; mt < 2; ++mt) {
                    mma_bf16(c[mt][nt], afh[mt], bfh);
                    mma_bf16(c[mt][nt], afh[mt], bfl);
                    mma_bf16(c[mt][nt], afl[mt], bfh);
                }
            }
        }
        __syncthreads();
    }

    float alpha = 0.f, beta = 0.f;
    if (mode == 2) {
        alpha = 1.f / (1.f + __expf(-skipP[0]));
        beta = 1.f - alpha;
    }
    int r = lane >> 2, cq = (lane & 3) * 2;
    #pragma unroll
    for (int mt = 0; mt < 2; ++mt) {
        #pragma unroll
        for (int nt = 0; nt < 8; ++nt) {
            int col = wn * 64 + nt * 8 + cq;
            #pragma unroll
            for (int half = 0; half < 2; ++half) {
                int row = m0 + wm * 32 + mt * 16 + r + half * 8;
                if (row < n) {
                    #pragma unroll
                    for (int q = 0; q < 2; ++q) {
                        float x = c[mt][nt][half * 2 + q] + bias[col + q];
                        if (mode == 1) x = tanhf(x);
                        else if (mode == 2) x = x * alpha + resid[(size_t)row * CD + col + q] * beta;
                        C[(size_t)row * CD + col + q] = x;
                    }
                }
            }
        }
    }
}

// ---------------- edge attention + aggregation: one warp per destination ----------------
__global__ void edge_kernel(const float* __restrict__ q, const float* __restrict__ kf,
                            const float* __restrict__ v, const float* __restrict__ vraw,
                            const int* __restrict__ src, const float* __restrict__ rp,
                            int rel, float* __restrict__ lt, float* __restrict__ ht) {
    int w = (blockIdx.x * blockDim.x + threadIdx.x) >> 5;
    int lane = threadIdx.x & 31;
    if (w >= NN) return;
    int head = lane >> 2;
    const int* eix = g_eidx[rel];
    int o0 = g_off[rel][w], o1 = g_off[rel][w + 1];

    float4 q4 = *reinterpret_cast<const float4*>(q + (size_t)w * CD + lane * 4);
    float sc = rp[head] * 0.25f;
    q4.x *= sc; q4.y *= sc; q4.z *= sc; q4.w *= sc;

    float m_l = NEG_BIG, m_h = NEG_BIG, z_l = 0.f, z_h = 0.f;
    for (int e = o0; e < o1; ++e) {
        int s = src[eix[e]];
        float4 k4 = *reinterpret_cast<const float4*>(kf + (size_t)s * CD + lane * 4);
        float p = q4.x * k4.x + q4.y * k4.y + q4.z * k4.z + q4.w * k4.w;
        p += __shfl_xor_sync(0xffffffffu, p, 1);
        p += __shfl_xor_sync(0xffffffffu, p, 2);
        float iv = 1.f / (p + 1e-6f);
        float mn = fmaxf(m_l, p);
        z_l = z_l * __expf(m_l - mn) + __expf(p - mn);
        m_l = mn;
        mn = fmaxf(m_h, iv);
        z_h = z_h * __expf(m_h - mn) + __expf(iv - mn);
        m_h = mn;
        if ((lane & 3) == 0) g_rawbuf[(size_t)e * 8 + head] = p;
    }
    __threadfence_block();
    __syncwarp();

    float izl = z_l > 0.f ? 1.f / z_l : 0.f;
    float izh = z_h > 0.f ? 1.f / z_h : 0.f;
    float4 al = make_float4(0.f, 0.f, 0.f, 0.f);
    float4 ah = make_float4(0.f, 0.f, 0.f, 0.f);
    for (int e = o0; e < o1; ++e) {
        int s = src[eix[e]];
        float raw = g_rawbuf[(size_t)e * 8 + head];
        float wl = __expf(raw - m_l) * izl;
        float wh = __expf(1.f / (raw + 1e-6f) - m_h) * izh;
        float4 v4 = *reinterpret_cast<const float4*>(v + (size_t)s * CD + lane * 4);
        al.x += v4.x * wl; al.y += v4.y * wl; al.z += v4.z * wl; al.w += v4.w * wl;
        ah.x += v4.x * wh; ah.y += v4.y * wh; ah.z += v4.z * wh; ah.w += v4.w * wh;
    }
    float4 o = *reinterpret_cast<const float4*>(vraw + (size_t)w * CD + lane * 4);
    float4 lo = make_float4(o.x + al.x, o.y + al.y, o.z + al.z, o.w + al.w);
    float4 ho = make_float4(o.x - ah.x, o.y - ah.y, o.z - ah.z, o.w - ah.w);
    *reinterpret_cast<float4*>(lt + (size_t)w * CD + lane * 4) = lo;
    *reinterpret_cast<float4*>(ht + (size_t)w * CD + lane * 4) = ho;
}

// ---------------- gating ----------------
__global__ void gate_kernel(const float* __restrict__ hz0, const float* __restrict__ hz1,
                            const float* __restrict__ xp, const float* __restrict__ ltb,
                            const float* __restrict__ htb, float* __restrict__ T) {
    int w = (blockIdx.x * blockDim.x + threadIdx.x) >> 5;
    int lane = threadIdx.x & 31;
    if (w >= NN) return;
    size_t base = (size_t)w * CD + lane * 4;
    float4 x  = *reinterpret_cast<const float4*>(xp + base);
    float4 h0 = *reinterpret_cast<const float4*>(hz0 + base);
    float4 h1 = *reinterpret_cast<const float4*>(hz1 + base);
    float s0 = h0.x * x.x + h0.y * x.y + h0.z * x.z + h0.w * x.w;
    float s1 = h1.x * x.x + h1.y * x.y + h1.z * x.z + h1.w * x.w;
    #pragma unroll
    for (int off = 16; off > 0; off >>= 1) {
        s0 += __shfl_xor_sync(0xffffffffu, s0, off);
        s1 += __shfl_xor_sync(0xffffffffu, s1, off);
    }
    float mx = fmaxf(s0, s1);
    float e0 = __expf(s0 - mx), e1 = __expf(s1 - mx);
    float r = 1.f / (e0 + e1);
    float c0 = e0 * r, c1 = e1 * r;
    float4 l = *reinterpret_cast<const float4*>(ltb + base);
    float4 h = *reinterpret_cast<const float4*>(htb + base);
    *reinterpret_cast<float4*>(T + base) =
        make_float4(l.x * c0 + h.x * c1, l.y * c0 + h.y * c1,
                    l.z * c0 + h.z * c1, l.w * c0 + h.w * c1);
}

// ---------------- host launcher ----------------
extern "C" void kernel_launch(void* const* d_in, const int* in_sizes, int n_in,
                              void* d_out, int out_size) {
    const float* h_user  = (const float*)d_in[0];
    const float* h_item  = (const float*)d_in[1];
    const int* buys_src  = (const int*)d_in[2];
    const int* buys_dst  = (const int*)d_in[3];
    const int* rev_src   = (const int*)d_in[4];
    const int* rev_dst   = (const int*)d_in[5];
    const float* Wk_u = (const float*)d_in[6];   const float* bk_u = (const float*)d_in[7];
    const float* Wk_i = (const float*)d_in[8];   const float* bk_i = (const float*)d_in[9];
    const float* Wq_u = (const float*)d_in[10];  const float* bq_u = (const float*)d_in[11];
    const float* Wq_i = (const float*)d_in[12];  const float* bq_i = (const float*)d_in[13];
    const float* Wv_u = (const float*)d_in[14];  const float* bv_u = (const float*)d_in[15];
    const float* Wv_i = (const float*)d_in[16];  const float* bv_i = (const float*)d_in[17];
    const float* Wa_u = (const float*)d_in[18];  const float* ba_u = (const float*)d_in[19];
    const float* Wa_i = (const float*)d_in[20];  const float* ba_i = (const float*)d_in[21];
    const float* Wf_  = (const float*)d_in[22];  const float* bf_  = (const float*)d_in[23];
    const float* Wx_  = (const float*)d_in[24];  const float* bx_  = (const float*)d_in[25];
    const float* rel_pri = (const float*)d_in[26];
    const float* rel_att = (const float*)d_in[27];
    const float* rel_msg = (const float*)d_in[28];
    const float* skip    = (const float*)d_in[29];
    (void)in_sizes; (void)n_in; (void)out_size;

    float* buf;    cudaGetSymbolAddress((void**)&buf, g_bufs);
    float* wfold;  cudaGetSymbolAddress((void**)&wfold, g_Wfold);
    float* bfold;  cudaGetSymbolAddress((void**)&bfold, g_bfold);
    __nv_bfloat16* wh; cudaGetSymbolAddress((void**)&wh, g_wh);
    __nv_bfloat16* wl; cudaGetSymbolAddress((void**)&wl, g_wl);
    auto B = [&](int i) { return buf + (size_t)i * NN * CD; };
    auto WH = [&](int i) { return wh + (size_t)i * CD * CD; };
    auto WL = [&](int i) { return wl + (size_t)i * CD * CD; };

    zero_kernel<<<(2 * NN + 255) / 256, 256>>>();
    fold_kernel<<<(4 * CD * CD + 255) / 256, 256>>>(Wk_u, bk_u, Wk_i, bk_i,
                                                    Wv_u, bv_u, Wv_i, bv_i,
                                                    rel_att, rel_msg);
    wprep_kernel<<<(12 * CD * CD + 255) / 256, 256>>>(Wq_u, Wq_i, Wv_u, Wv_i,
                                                      Wf_, Wx_, Wa_u, Wa_i);
    count_kernel<<<(2 * EE + 255) / 256, 256>>>(buys_dst, rev_dst);
    scan_a<<<dim3(SCAN_NB, 2), SCAN_B>>>();
    scan_b<<<1, 64>>>();
    scan_c<<<dim3(SCAN_NB, 2), SCAN_B>>>();
    scatter_kernel<<<(2 * EE + 255) / 256, 256>>>(buys_dst, rev_dst);

    dim3 gg((NN + 127) / 128);
    // Q/K GEMMs in full fp32 (precision-critical: feed 1/(raw+eps) softmax)
    gemm128_f32<<<gg, 256>>>(h_user, wfold + 0 * CD * CD, bfold + 0 * CD, B(0), NN); // Kf_u
    gemm128_f32<<<gg, 256>>>(h_item, wfold + 1 * CD * CD, bfold + 1 * CD, B(1), NN); // Kf_i
    gemm128_f32<<<gg, 256>>>(h_item, Wq_i, bq_i, B(2), NN);                          // Q_i
    gemm128_f32<<<gg, 256>>>(h_user, Wq_u, bq_u, B(3), NN);                          // Q_u
    // remaining GEMMs in bf16x3 tensor core
    gemm128_tc<<<gg, 256>>>(h_user, WH(2), WL(2), bfold + 2 * CD, B(4), NN, 0, nullptr, nullptr); // Vm_u
    gemm128_tc<<<gg, 256>>>(h_item, WH(3), WL(3), bfold + 3 * CD, B(5), NN, 0, nullptr, nullptr); // Vm_i
    gemm128_tc<<<gg, 256>>>(h_user, WH(6), WL(6), bv_u, B(6), NN, 0, nullptr, nullptr);           // Vraw_u
    gemm128_tc<<<gg, 256>>>(h_item, WH(7), WL(7), bv_i, B(7), NN, 0, nullptr, nullptr);           // Vraw_i

    int wb = (NN * 32 + 255) / 256;
    edge_kernel<<<wb, 256>>>(B(2), B(0), B(4), B(7), buys_src, rel_pri + 0, 0, B(10), B(11));
    edge_kernel<<<wb, 256>>>(B(3), B(1), B(5), B(6), rev_src, rel_pri + 8, 1, B(8), B(9));

    float* out = (float*)d_out;
    for (int t = 0; t < 2; ++t) {
        const float* LT = (t == 0) ? B(8)  : B(10);
        const float* HT = (t == 0) ? B(9)  : B(11);
        const float* VR = (t == 0) ? B(6)  : B(7);
        const float* hn = (t == 0) ? h_user : h_item;
        const float* ba = (t == 0) ? ba_u : ba_i;
        int wa = (t == 0) ? 10 : 11;
        gemm128_tc<<<gg, 256>>>(LT, WH(8), WL(8), bf_, B(12), NN, 1, nullptr, nullptr); // HZ0
        gemm128_tc<<<gg, 256>>>(HT, WH(8), WL(8), bf_, B(13), NN, 1, nullptr, nullptr); // HZ1
        gemm128_tc<<<gg, 256>>>(VR, WH(9), WL(9), bx_, B(14), NN, 1, nullptr, nullptr); // XP
        gate_kernel<<<wb, 256>>>(B(12), B(13), B(14), LT, HT, B(15));                   // T
        gemm128_tc<<<gg, 256>>>(B(15), WH(wa), WL(wa), ba, out + (size_t)t * NN * CD, NN, 2, hn, skip + t);
    }
}

// round 7
// speedup vs baseline: 1.4149x; 1.2734x over previous
#include <cuda_runtime.h>
#include <cuda_bf16.h>

#define NN 50000
#define EE 400000
#define CD 128
#define NEG_BIG (-3.402823466e38f)
#define SCAN_B 512
#define SCAN_NB ((NN + SCAN_B - 1) / SCAN_B)

// ---------------- device scratch (static, no allocations) ----------------
// fp32 buffers: 0:Kf_u 1:Kf_i 2:Q_i 3:Q_u 4:Vm_u 5:Vm_i 6:Vraw_u 7:Vraw_i
// 8:LT_u 9:HT_u 10:LT_i 11:HT_i 12:HZ0_t0 13:HZ1_t0 14:XP_t0 15:unused
// (t=1 chain reuses 0,1,2 after Q/K are dead)
__device__ float g_bufs[16][NN * CD];
__device__ float g_rawbuf[2][(size_t)EE * 8];
__device__ int   g_cnt[2][NN];
__device__ int   g_cur[2][NN];
__device__ int   g_off[2][NN + 1];
__device__ int   g_eidx[2][EE];
__device__ int   g_bsum[2][SCAN_NB];
__device__ float g_Wfold[4][CD * CD];
__device__ float g_bfold[4][CD];
// TRANSPOSED bf16 hi/lo weights [n][k]: slots 2,3 folded Vm_u/Vm_i; 6:Wv_u 7:Wv_i 8:Wf 9:Wx 10:Wa_u 11:Wa_i
__device__ __nv_bfloat16 g_wh[12][CD * CD];
__device__ __nv_bfloat16 g_wl[12][CD * CD];
// bf16 hi/lo activation pairs:
// 0:h_user 1:h_item 2:LT_u 3:HT_u 4:LT_i 5:HT_i 6:VR_u 7:VR_i 8:T_u 9:T_i
__device__ __nv_bfloat16 g_bh[10][NN * CD];
__device__ __nv_bfloat16 g_bl[10][NN * CD];

// ---------------- small kernels ----------------
__global__ void zero_kernel() {
    int i = blockIdx.x * blockDim.x + threadIdx.x;
    if (i < 2 * NN) {
        (&g_cnt[0][0])[i] = 0;
        (&g_cur[0][0])[i] = 0;
    }
}

// Fold relation transforms into linear weights (fp32).
__global__ void fold_kernel(const float* __restrict__ Wk_u, const float* __restrict__ bk_u,
                            const float* __restrict__ Wk_i, const float* __restrict__ bk_i,
                            const float* __restrict__ Wv_u, const float* __restrict__ bv_u,
                            const float* __restrict__ Wv_i, const float* __restrict__ bv_i,
                            const float* __restrict__ rel_att, const float* __restrict__ rel_msg) {
    int idx = blockIdx.x * blockDim.x + threadIdx.x;
    if (idx >= 4 * CD * CD) return;
    int f = idx >> 14;
    int r = idx & 16383;
    int i = r >> 7;
    int c = r & 127;
    int h = c >> 4, kk = c & 15;
    const float* W; const float* b; const float* R;
    if (f == 0)      { W = Wk_u; b = bk_u; R = rel_att; }
    else if (f == 1) { W = Wk_i; b = bk_i; R = rel_att + 2048; }
    else if (f == 2) { W = Wv_u; b = bv_u; R = rel_msg; }
    else             { W = Wv_i; b = bv_i; R = rel_msg + 2048; }
    float s = 0.f;
    #pragma unroll
    for (int j = 0; j < 16; ++j)
        s += W[i * CD + h * 16 + j] * R[h * 256 + j * 16 + kk];
    g_Wfold[f][i * CD + c] = s;
    if (i == 0) {
        float sb = 0.f;
        #pragma unroll
        for (int j = 0; j < 16; ++j)
            sb += b[h * 16 + j] * R[h * 256 + j * 16 + kk];
        g_bfold[f][c] = sb;
    }
}

// Convert the 8 TC weight matrices to bf16 hi/lo, stored TRANSPOSED [n][k].
__global__ void wprep_kernel(const float* __restrict__ Wv_u, const float* __restrict__ Wv_i,
                             const float* __restrict__ Wf, const float* __restrict__ Wx,
                             const float* __restrict__ Wa_u, const float* __restrict__ Wa_i) {
    int idx = blockIdx.x * blockDim.x + threadIdx.x;
    if (idx >= 8 * CD * CD) return;
    int wsel = idx >> 14, r = idx & 16383;
    int kk = r >> 7, nn = r & 127;
    const float* src; int slot;
    switch (wsel) {
        case 0: src = g_Wfold[2]; slot = 2; break;
        case 1: src = g_Wfold[3]; slot = 3; break;
        case 2: src = Wv_u; slot = 6; break;
        case 3: src = Wv_i; slot = 7; break;
        case 4: src = Wf;   slot = 8; break;
        case 5: src = Wx;   slot = 9; break;
        case 6: src = Wa_u; slot = 10; break;
        default: src = Wa_i; slot = 11; break;
    }
    float x = src[r];
    __nv_bfloat16 h = __float2bfloat16(x);
    g_wh[slot][nn * CD + kk] = h;
    g_wl[slot][nn * CD + kk] = __float2bfloat16(x - __bfloat162float(h));
}

// Convert node features to bf16 hi/lo pairs (slots 0,1).
__global__ void hprep_kernel(const float* __restrict__ hu, const float* __restrict__ hi_) {
    int idx = blockIdx.x * blockDim.x + threadIdx.x;
    if (idx >= 2 * NN * CD) return;
    int slot = idx < NN * CD ? 0 : 1;
    int r = idx - slot * NN * CD;
    float x = (slot ? hi_ : hu)[r];
    __nv_bfloat16 h = __float2bfloat16(x);
    g_bh[slot][r] = h;
    g_bl[slot][r] = __float2bfloat16(x - __bfloat162float(h));
}

__global__ void count_kernel(const int* __restrict__ bd, const int* __restrict__ rd) {
    int i = blockIdx.x * blockDim.x + threadIdx.x;
    if (i >= 2 * EE) return;
    if (i < EE) atomicAdd(&g_cnt[0][bd[i]], 1);
    else        atomicAdd(&g_cnt[1][rd[i - EE]], 1);
}

// --- 3-phase scan ---
__global__ void scan_a() {
    int rel = blockIdx.y;
    int i = blockIdx.x * SCAN_B + threadIdx.x;
    __shared__ int sh[SCAN_B];
    int v = (i < NN) ? g_cnt[rel][i] : 0;
    sh[threadIdx.x] = v;
    __syncthreads();
    for (int off = 1; off < SCAN_B; off <<= 1) {
        int t = (threadIdx.x >= off) ? sh[threadIdx.x - off] : 0;
        __syncthreads();
        sh[threadIdx.x] += t;
        __syncthreads();
    }
    if (i < NN) g_off[rel][i] = sh[threadIdx.x] - v;
    if (threadIdx.x == SCAN_B - 1) g_bsum[rel][blockIdx.x] = sh[SCAN_B - 1];
}

__global__ void scan_b() {
    int rel = threadIdx.x >> 5;
    int lane = threadIdx.x & 31;
    if (rel >= 2) return;
    int base = lane * 4;
    int v[4];
    int tot = 0;
    #pragma unroll
    for (int j = 0; j < 4; ++j) {
        v[j] = (base + j < SCAN_NB) ? g_bsum[rel][base + j] : 0;
        tot += v[j];
    }
    int inc = tot;
    #pragma unroll
    for (int off = 1; off < 32; off <<= 1) {
        int t = __shfl_up_sync(0xffffffffu, inc, off);
        if (lane >= off) inc += t;
    }
    int run = inc - tot;
    #pragma unroll
    for (int j = 0; j < 4; ++j) {
        if (base + j < SCAN_NB) g_bsum[rel][base + j] = run;
        run += v[j];
    }
    if (lane == 31) g_off[rel][NN] = inc;
}

__global__ void scan_c() {
    int rel = blockIdx.y;
    int i = blockIdx.x * SCAN_B + threadIdx.x;
    if (i < NN) g_off[rel][i] += g_bsum[rel][blockIdx.x];
}

__global__ void scatter_kernel(const int* __restrict__ bd, const int* __restrict__ rd) {
    int i = blockIdx.x * blockDim.x + threadIdx.x;
    if (i >= 2 * EE) return;
    int rel = i < EE ? 0 : 1;
    int e   = i < EE ? i : i - EE;
    int dst = rel ? rd[e] : bd[e];
    int pos = atomicAdd(&g_cur[rel][dst], 1);
    g_eidx[rel][g_off[rel][dst] + pos] = e;
}

// ---------------- fp32 SIMT GEMM (precision-critical Q/K path) ----------------
__global__ __launch_bounds__(256, 2) void gemm128_f32(
    const float* __restrict__ A, const float* __restrict__ W,
    const float* __restrict__ bias, float* __restrict__ C, int n) {
    __shared__ float As[128][33];
    __shared__ float Ws[32][128];
    int tid = threadIdx.x;
    int tx = tid & 15, ty = tid >> 4;
    int m0 = blockIdx.x * 128;

    float acc[8][8];
    #pragma unroll
    for (int i = 0; i < 8; ++i)
        #pragma unroll
        for (int j = 0; j < 8; ++j) acc[i][j] = 0.f;

    for (int kc = 0; kc < 4; ++kc) {
        #pragma unroll
        for (int l = 0; l < 4; ++l) {
            int lin = tid + l * 256;
            int row = lin >> 3, kq = lin & 7;
            float4 a4 = make_float4(0.f, 0.f, 0.f, 0.f);
            if (m0 + row < n)
                a4 = *reinterpret_cast<const float4*>(A + (size_t)(m0 + row) * CD + kc * 32 + kq * 4);
            As[row][kq * 4 + 0] = a4.x;
            As[row][kq * 4 + 1] = a4.y;
            As[row][kq * 4 + 2] = a4.z;
            As[row][kq * 4 + 3] = a4.w;
        }
        #pragma unroll
        for (int l = 0; l < 4; ++l) {
            int lin = tid + l * 256;
            int kr = lin >> 5, c4 = lin & 31;
            *reinterpret_cast<float4*>(&Ws[kr][c4 * 4]) =
                *reinterpret_cast<const float4*>(W + (size_t)(kc * 32 + kr) * CD + c4 * 4);
        }
        __syncthreads();
        #pragma unroll
        for (int k = 0; k < 32; ++k) {
            float a[8], b[8];
            #pragma unroll
            for (int i = 0; i < 8; ++i) a[i] = As[ty + 16 * i][k];
            #pragma unroll
            for (int j = 0; j < 8; ++j) b[j] = Ws[k][tx + 16 * j];
            #pragma unroll
            for (int i = 0; i < 8; ++i)
                #pragma unroll
                for (int j = 0; j < 8; ++j) acc[i][j] += a[i] * b[j];
        }
        __syncthreads();
    }

    #pragma unroll
    for (int i = 0; i < 8; ++i) {
        int row = m0 + ty + 16 * i;
        if (row < n) {
            #pragma unroll
            for (int j = 0; j < 8; ++j) {
                int col = tx + 16 * j;
                C[(size_t)row * CD + col] = acc[i][j] + bias[col];
            }
        }
    }
}

// ---------------- bf16x3 tensor-core GEMM, pure-bf16 operands ----------------
// A given as pre-split hi/lo bf16 [n,128] row-major; W pre-split TRANSPOSED [128n][128k].
// mode 0: none; 1: tanh; 2: x*sigmoid(skip)+resid*(1-sig). Optional bf16 pair output.
#define BKP 40   // 32 + 8 pad: keeps 16B-aligned rows (80B) and conflict-free fragments

__device__ __forceinline__ void mma_bf16(float* c, const unsigned* a, const unsigned* b) {
    asm volatile("mma.sync.aligned.m16n8k16.row.col.f32.bf16.bf16.f32 "
        "{%0,%1,%2,%3}, {%4,%5,%6,%7}, {%8,%9}, {%0,%1,%2,%3};"
        : "+f"(c[0]), "+f"(c[1]), "+f"(c[2]), "+f"(c[3])
        : "r"(a[0]), "r"(a[1]), "r"(a[2]), "r"(a[3]), "r"(b[0]), "r"(b[1]));
}

__global__ __launch_bounds__(256, 2) void gemm128_bf16(
    const __nv_bfloat16* __restrict__ Ah_g, const __nv_bfloat16* __restrict__ Al_g,
    const __nv_bfloat16* __restrict__ Wh, const __nv_bfloat16* __restrict__ Wl,
    const float* __restrict__ bias, float* __restrict__ C,
    __nv_bfloat16* __restrict__ Oh, __nv_bfloat16* __restrict__ Ol,
    int n, int mode, const float* __restrict__ resid, const float* __restrict__ skipP) {
    __shared__ __nv_bfloat16 Ah[128][BKP];
    __shared__ __nv_bfloat16 Al[128][BKP];
    __shared__ __nv_bfloat16 Bh[128][BKP];
    __shared__ __nv_bfloat16 Bl[128][BKP];

    int tid = threadIdx.x;
    int lane = tid & 31;
    int wid = tid >> 5;
    int wm = wid & 3;
    int wn = wid >> 2;
    int m0 = blockIdx.x * 128;

    float c[2][8][4];
    #pragma unroll
    for (int i = 0; i < 2; ++i)
        #pragma unroll
        for (int j = 0; j < 8; ++j)
            #pragma unroll
            for (int q = 0; q < 4; ++q) c[i][j][q] = 0.f;

    const uint4 zero4 = make_uint4(0u, 0u, 0u, 0u);
    for (int kc = 0; kc < 4; ++kc) {
        // A tile: 128 rows x 32 bf16 = 512 uint4 per matrix (hi+lo)
        #pragma unroll
        for (int l = 0; l < 2; ++l) {
            int idx = tid + l * 256;
            int row = idx >> 2, q = idx & 3;
            size_t goff = (size_t)(m0 + row) * CD + kc * 32 + q * 8;
            uint4 vh = zero4, vl = zero4;
            if (m0 + row < n) {
                vh = *reinterpret_cast<const uint4*>(Ah_g + goff);
                vl = *reinterpret_cast<const uint4*>(Al_g + goff);
            }
            *reinterpret_cast<uint4*>(&Ah[row][q * 8]) = vh;
            *reinterpret_cast<uint4*>(&Al[row][q * 8]) = vl;
        }
        // B tile (transposed weights): rows = n-index, 32 contiguous k
        #pragma unroll
        for (int l = 0; l < 2; ++l) {
            int idx = tid + l * 256;
            int row = idx >> 2, q = idx & 3;
            size_t goff = (size_t)row * CD + kc * 32 + q * 8;
            *reinterpret_cast<uint4*>(&Bh[row][q * 8]) =
                *reinterpret_cast<const uint4*>(Wh + goff);
            *reinterpret_cast<uint4*>(&Bl[row][q * 8]) =
                *reinterpret_cast<const uint4*>(Wl + goff);
        }
        __syncthreads();

        #pragma unroll
        for (int ks = 0; ks < 2; ++ks) {
            int kb = ks * 16;
            int r = lane >> 2, cq = (lane & 3) * 2;
            unsigned afh[2][4], afl[2][4];
            #pragma unroll
            for (int mt = 0; mt < 2; ++mt) {
                int row = wm * 32 + mt * 16 + r;
                afh[mt][0] = *reinterpret_cast<const unsigned*>(&Ah[row][kb + cq]);
                afh[mt][1] = *reinterpret_cast<const unsigned*>(&Ah[row + 8][kb + cq]);
                afh[mt][2] = *reinterpret_cast<const unsigned*>(&Ah[row][kb + cq + 8]);
                afh[mt][3] = *reinterpret_cast<const unsigned*>(&Ah[row + 8][kb + cq + 8]);
                afl[mt][0] = *reinterpret_cast<const unsigned*>(&Al[row][kb + cq]);
                afl[mt][1] = *reinterpret_cast<const unsigned*>(&Al[row + 8][kb + cq]);
                afl[mt][2] = *reinterpret_cast<const unsigned*>(&Al[row][kb + cq + 8]);
                afl[mt][3] = *reinterpret_cast<const unsigned*>(&Al[row + 8][kb + cq + 8]);
            }
            #pragma unroll
            for (int nt = 0; nt < 8; ++nt) {
                int col = wn * 64 + nt * 8 + (lane >> 2);
                unsigned bfh[2], bfl[2];
                bfh[0] = *reinterpret_cast<const unsigned*>(&Bh[col][kb + cq]);
                bfh[1] = *reinterpret_cast<const unsigned*>(&Bh[col][kb + cq + 8]);
                bfl[0] = *reinterpret_cast<const unsigned*>(&Bl[col][kb + cq]);
                bfl[1] = *reinterpret_cast<const unsigned*>(&Bl[col][kb + cq + 8]);
                #pragma unroll
                for (int mt = 0; mt < 2; ++mt) {
                    mma_bf16(c[mt][nt], afh[mt], bfh);
                    mma_bf16(c[mt][nt], afh[mt], bfl);
                    mma_bf16(c[mt][nt], afl[mt], bfh);
                }
            }
        }
        __syncthreads();
    }

    float alpha = 0.f, beta = 0.f;
    if (mode == 2) {
        alpha = 1.f / (1.f + __expf(-skipP[0]));
        beta = 1.f - alpha;
    }
    int r = lane >> 2, cq = (lane & 3) * 2;
    #pragma unroll
    for (int mt = 0; mt < 2; ++mt) {
        #pragma unroll
        for (int nt = 0; nt < 8; ++nt) {
            int col = wn * 64 + nt * 8 + cq;
            #pragma unroll
            for (int half = 0; half < 2; ++half) {
                int row = m0 + wm * 32 + mt * 16 + r + half * 8;
                if (row < n) {
                    float x0 = c[mt][nt][half * 2 + 0] + bias[col];
                    float x1 = c[mt][nt][half * 2 + 1] + bias[col + 1];
                    if (mode == 1) { x0 = tanhf(x0); x1 = tanhf(x1); }
                    else if (mode == 2) {
                        x0 = x0 * alpha + resid[(size_t)row * CD + col] * beta;
                        x1 = x1 * alpha + resid[(size_t)row * CD + col + 1] * beta;
                    }
                    C[(size_t)row * CD + col] = x0;
                    C[(size_t)row * CD + col + 1] = x1;
                    if (Oh) {
                        __nv_bfloat16 h0 = __float2bfloat16(x0);
                        __nv_bfloat16 h1 = __float2bfloat16(x1);
                        __nv_bfloat162 hh; hh.x = h0; hh.y = h1;
                        *reinterpret_cast<__nv_bfloat162*>(Oh + (size_t)row * CD + col) = hh;
                        __nv_bfloat162 ll;
                        ll.x = __float2bfloat16(x0 - __bfloat162float(h0));
                        ll.y = __float2bfloat16(x1 - __bfloat162float(h1));
                        *reinterpret_cast<__nv_bfloat162*>(Ol + (size_t)row * CD + col) = ll;
                    }
                }
            }
        }
    }
}

// ---------------- edge attention + aggregation: one warp per destination ----------------
// Emits lt/ht fp32 AND pre-split bf16 hi/lo (A operands for the HZ GEMMs).
__global__ void edge_kernel(const float* __restrict__ q, const float* __restrict__ kf,
                            const float* __restrict__ v, const float* __restrict__ vraw,
                            const int* __restrict__ src, const float* __restrict__ rp,
                            int rel, float* __restrict__ lt, float* __restrict__ ht,
                            __nv_bfloat16* __restrict__ lth, __nv_bfloat16* __restrict__ ltl,
                            __nv_bfloat16* __restrict__ hth, __nv_bfloat16* __restrict__ htl) {
    int w = (blockIdx.x * blockDim.x + threadIdx.x) >> 5;
    int lane = threadIdx.x & 31;
    if (w >= NN) return;
    int head = lane >> 2;
    const int* eix = g_eidx[rel];
    float* rawb = g_rawbuf[rel];
    int o0 = g_off[rel][w], o1 = g_off[rel][w + 1];

    float4 q4 = *reinterpret_cast<const float4*>(q + (size_t)w * CD + lane * 4);
    float sc = rp[head] * 0.25f;
    q4.x *= sc; q4.y *= sc; q4.z *= sc; q4.w *= sc;

    float m_l = NEG_BIG, m_h = NEG_BIG, z_l = 0.f, z_h = 0.f;
    for (int e = o0; e < o1; ++e) {
        int s = src[eix[e]];
        float4 k4 = *reinterpret_cast<const float4*>(kf + (size_t)s * CD + lane * 4);
        float p = q4.x * k4.x + q4.y * k4.y + q4.z * k4.z + q4.w * k4.w;
        p += __shfl_xor_sync(0xffffffffu, p, 1);
        p += __shfl_xor_sync(0xffffffffu, p, 2);
        float iv = 1.f / (p + 1e-6f);
        float mn = fmaxf(m_l, p);
        z_l = z_l * __expf(m_l - mn) + __expf(p - mn);
        m_l = mn;
        mn = fmaxf(m_h, iv);
        z_h = z_h * __expf(m_h - mn) + __expf(iv - mn);
        m_h = mn;
        if ((lane & 3) == 0) rawb[(size_t)e * 8 + head] = p;
    }
    __threadfence_block();
    __syncwarp();

    float izl = z_l > 0.f ? 1.f / z_l : 0.f;
    float izh = z_h > 0.f ? 1.f / z_h : 0.f;
    float4 al = make_float4(0.f, 0.f, 0.f, 0.f);
    float4 ah = make_float4(0.f, 0.f, 0.f, 0.f);
    for (int e = o0; e < o1; ++e) {
        int s = src[eix[e]];
        float raw = rawb[(size_t)e * 8 + head];
        float wl = __expf(raw - m_l) * izl;
        float wh = __expf(1.f / (raw + 1e-6f) - m_h) * izh;
        float4 v4 = *reinterpret_cast<const float4*>(v + (size_t)s * CD + lane * 4);
        al.x += v4.x * wl; al.y += v4.y * wl; al.z += v4.z * wl; al.w += v4.w * wl;
        ah.x += v4.x * wh; ah.y += v4.y * wh; ah.z += v4.z * wh; ah.w += v4.w * wh;
    }
    float4 o = *reinterpret_cast<const float4*>(vraw + (size_t)w * CD + lane * 4);
    float4 lo = make_float4(o.x + al.x, o.y + al.y, o.z + al.z, o.w + al.w);
    float4 ho = make_float4(o.x - ah.x, o.y - ah.y, o.z - ah.z, o.w - ah.w);
    size_t base = (size_t)w * CD + lane * 4;
    *reinterpret_cast<float4*>(lt + base) = lo;
    *reinterpret_cast<float4*>(ht + base) = ho;

    // bf16 hi/lo emits
    float lv[4] = {lo.x, lo.y, lo.z, lo.w};
    float hv[4] = {ho.x, ho.y, ho.z, ho.w};
    #pragma unroll
    for (int p2 = 0; p2 < 2; ++p2) {
        __nv_bfloat162 hh, ll;
        hh.x = __float2bfloat16(lv[p2 * 2]);     hh.y = __float2bfloat16(lv[p2 * 2 + 1]);
        ll.x = __float2bfloat16(lv[p2 * 2] - __bfloat162float(hh.x));
        ll.y = __float2bfloat16(lv[p2 * 2 + 1] - __bfloat162float(hh.y));
        *reinterpret_cast<__nv_bfloat162*>(lth + base + p2 * 2) = hh;
        *reinterpret_cast<__nv_bfloat162*>(ltl + base + p2 * 2) = ll;
        hh.x = __float2bfloat16(hv[p2 * 2]);     hh.y = __float2bfloat16(hv[p2 * 2 + 1]);
        ll.x = __float2bfloat16(hv[p2 * 2] - __bfloat162float(hh.x));
        ll.y = __float2bfloat16(hv[p2 * 2 + 1] - __bfloat162float(hh.y));
        *reinterpret_cast<__nv_bfloat162*>(hth + base + p2 * 2) = hh;
        *reinterpret_cast<__nv_bfloat162*>(htl + base + p2 * 2) = ll;
    }
}

// ---------------- gating: emits T as bf16 hi/lo pair ----------------
__global__ void gate_kernel(const float* __restrict__ hz0, const float* __restrict__ hz1,
                            const float* __restrict__ xp, const float* __restrict__ ltb,
                            const float* __restrict__ htb,
                            __nv_bfloat16* __restrict__ Th, __nv_bfloat16* __restrict__ Tl) {
    int w = (blockIdx.x * blockDim.x + threadIdx.x) >> 5;
    int lane = threadIdx.x & 31;
    if (w >= NN) return;
    size_t base = (size_t)w * CD + lane * 4;
    float4 x  = *reinterpret_cast<const float4*>(xp + base);
    float4 h0 = *reinterpret_cast<const float4*>(hz0 + base);
    float4 h1 = *reinterpret_cast<const float4*>(hz1 + base);
    float s0 = h0.x * x.x + h0.y * x.y + h0.z * x.z + h0.w * x.w;
    float s1 = h1.x * x.x + h1.y * x.y + h1.z * x.z + h1.w * x.w;
    #pragma unroll
    for (int off = 16; off > 0; off >>= 1) {
        s0 += __shfl_xor_sync(0xffffffffu, s0, off);
        s1 += __shfl_xor_sync(0xffffffffu, s1, off);
    }
    float mx = fmaxf(s0, s1);
    float e0 = __expf(s0 - mx), e1 = __expf(s1 - mx);
    float r = 1.f / (e0 + e1);
    float c0 = e0 * r, c1 = e1 * r;
    float4 l = *reinterpret_cast<const float4*>(ltb + base);
    float4 h = *reinterpret_cast<const float4*>(htb + base);
    float tv[4] = {l.x * c0 + h.x * c1, l.y * c0 + h.y * c1,
                   l.z * c0 + h.z * c1, l.w * c0 + h.w * c1};
    #pragma unroll
    for (int p2 = 0; p2 < 2; ++p2) {
        __nv_bfloat162 hh, ll;
        hh.x = __float2bfloat16(tv[p2 * 2]);     hh.y = __float2bfloat16(tv[p2 * 2 + 1]);
        ll.x = __float2bfloat16(tv[p2 * 2] - __bfloat162float(hh.x));
        ll.y = __float2bfloat16(tv[p2 * 2 + 1] - __bfloat162float(hh.y));
        *reinterpret_cast<__nv_bfloat162*>(Th + base + p2 * 2) = hh;
        *reinterpret_cast<__nv_bfloat162*>(Tl + base + p2 * 2) = ll;
    }
}

// ---------------- host launcher (fork/join streams, graph-capturable) ----------------
extern "C" void kernel_launch(void* const* d_in, const int* in_sizes, int n_in,
                              void* d_out, int out_size) {
    const float* h_user  = (const float*)d_in[0];
    const float* h_item  = (const float*)d_in[1];
    const int* buys_src  = (const int*)d_in[2];
    const int* buys_dst  = (const int*)d_in[3];
    const int* rev_src   = (const int*)d_in[4];
    const int* rev_dst   = (const int*)d_in[5];
    const float* Wk_u = (const float*)d_in[6];   const float* bk_u = (const float*)d_in[7];
    const float* Wk_i = (const float*)d_in[8];   const float* bk_i = (const float*)d_in[9];
    const float* Wq_u = (const float*)d_in[10];  const float* bq_u = (const float*)d_in[11];
    const float* Wq_i = (const float*)d_in[12];  const float* bq_i = (const float*)d_in[13];
    const float* Wv_u = (const float*)d_in[14];  const float* bv_u = (const float*)d_in[15];
    const float* Wv_i = (const float*)d_in[16];  const float* bv_i = (const float*)d_in[17];
    const float* Wa_u = (const float*)d_in[18];  const float* ba_u = (const float*)d_in[19];
    const float* Wa_i = (const float*)d_in[20];  const float* ba_i = (const float*)d_in[21];
    const float* Wf_  = (const float*)d_in[22];  const float* bf_  = (const float*)d_in[23];
    const float* Wx_  = (const float*)d_in[24];  const float* bx_  = (const float*)d_in[25];
    const float* rel_pri = (const float*)d_in[26];
    const float* rel_att = (const float*)d_in[27];
    const float* rel_msg = (const float*)d_in[28];
    const float* skip    = (const float*)d_in[29];
    (void)in_sizes; (void)n_in; (void)out_size;

    float* buf;    cudaGetSymbolAddress((void**)&buf, g_bufs);
    float* wfold;  cudaGetSymbolAddress((void**)&wfold, g_Wfold);
    float* bfold;  cudaGetSymbolAddress((void**)&bfold, g_bfold);
    __nv_bfloat16* wh; cudaGetSymbolAddress((void**)&wh, g_wh);
    __nv_bfloat16* wl; cudaGetSymbolAddress((void**)&wl, g_wl);
    __nv_bfloat16* bh; cudaGetSymbolAddress((void**)&bh, g_bh);
    __nv_bfloat16* bl; cudaGetSymbolAddress((void**)&bl, g_bl);
    auto B  = [&](int i) { return buf + (size_t)i * NN * CD; };
    auto WH = [&](int i) { return wh + (size_t)i * CD * CD; };
    auto WL = [&](int i) { return wl + (size_t)i * CD * CD; };
    auto BH = [&](int i) { return bh + (size_t)i * NN * CD; };
    auto BL = [&](int i) { return bl + (size_t)i * NN * CD; };

    static cudaStream_t sA = nullptr, sB = nullptr;
    static cudaEvent_t ev[7];
    if (!sA) {
        cudaStreamCreateWithFlags(&sA, cudaStreamNonBlocking);
        cudaStreamCreateWithFlags(&sB, cudaStreamNonBlocking);
        for (int i = 0; i < 7; ++i)
            cudaEventCreateWithFlags(&ev[i], cudaEventDisableTiming);
    }
    cudaStream_t s0 = 0;

    dim3 gg((NN + 127) / 128);
    int wb = (NN * 32 + 255) / 256;

    // fork
    cudaEventRecord(ev[0], s0);
    cudaStreamWaitEvent(sA, ev[0], 0);
    cudaStreamWaitEvent(sB, ev[0], 0);

    // ---- s0: fold -> fp32 Q/K GEMM chain (critical path) ----
    fold_kernel<<<(4 * CD * CD + 255) / 256, 256, 0, s0>>>(
        Wk_u, bk_u, Wk_i, bk_i, Wv_u, bv_u, Wv_i, bv_i, rel_att, rel_msg);
    cudaEventRecord(ev[1], s0);   // fold done (wprep dep)
    gemm128_f32<<<gg, 256, 0, s0>>>(h_user, wfold + 0 * CD * CD, bfold + 0 * CD, B(0), NN); // Kf_u
    gemm128_f32<<<gg, 256, 0, s0>>>(h_item, wfold + 1 * CD * CD, bfold + 1 * CD, B(1), NN); // Kf_i
    gemm128_f32<<<gg, 256, 0, s0>>>(h_item, Wq_i, bq_i, B(2), NN);                          // Q_i
    gemm128_f32<<<gg, 256, 0, s0>>>(h_user, Wq_u, bq_u, B(3), NN);                          // Q_u

    // ---- sA: CSR build ----
    zero_kernel<<<(2 * NN + 255) / 256, 256, 0, sA>>>();
    count_kernel<<<(2 * EE + 255) / 256, 256, 0, sA>>>(buys_dst, rev_dst);
    scan_a<<<dim3(SCAN_NB, 2), SCAN_B, 0, sA>>>();
    scan_b<<<1, 64, 0, sA>>>();
    scan_c<<<dim3(SCAN_NB, 2), SCAN_B, 0, sA>>>();
    scatter_kernel<<<(2 * EE + 255) / 256, 256, 0, sA>>>(buys_dst, rev_dst);
    cudaEventRecord(ev[2], sA);

    // ---- sB: prep + bf16 feature GEMMs ----
    hprep_kernel<<<(2 * NN * CD + 255) / 256, 256, 0, sB>>>(h_user, h_item);
    cudaStreamWaitEvent(sB, ev[1], 0);
    wprep_kernel<<<(8 * CD * CD + 255) / 256, 256, 0, sB>>>(Wv_u, Wv_i, Wf_, Wx_, Wa_u, Wa_i);
    gemm128_bf16<<<gg, 256, 0, sB>>>(BH(0), BL(0), WH(2), WL(2), bfold + 2 * CD, B(4),
                                     nullptr, nullptr, NN, 0, nullptr, nullptr);  // Vm_u
    gemm128_bf16<<<gg, 256, 0, sB>>>(BH(1), BL(1), WH(3), WL(3), bfold + 3 * CD, B(5),
                                     nullptr, nullptr, NN, 0, nullptr, nullptr);  // Vm_i
    gemm128_bf16<<<gg, 256, 0, sB>>>(BH(0), BL(0), WH(6), WL(6), bv_u, B(6),
                                     BH(6), BL(6), NN, 0, nullptr, nullptr);      // Vraw_u (+bf16)
    gemm128_bf16<<<gg, 256, 0, sB>>>(BH(1), BL(1), WH(7), WL(7), bv_i, B(7),
                                     BH(7), BL(7), NN, 0, nullptr, nullptr);      // Vraw_i (+bf16)
    cudaEventRecord(ev[3], sB);

    // ---- join before edges ----
    cudaStreamWaitEvent(s0, ev[2], 0);
    cudaStreamWaitEvent(s0, ev[3], 0);
    cudaEventRecord(ev[4], s0);
    cudaStreamWaitEvent(sB, ev[4], 0);

    // edges in parallel: rel1 (writes user LT/HT) on s0; rel0 (item) on sB
    edge_kernel<<<wb, 256, 0, s0>>>(B(3), B(1), B(5), B(6), rev_src, rel_pri + 8, 1,
                                    B(8), B(9), BH(2), BL(2), BH(3), BL(3));
    edge_kernel<<<wb, 256, 0, sB>>>(B(2), B(0), B(4), B(7), buys_src, rel_pri + 0, 0,
                                    B(10), B(11), BH(4), BL(4), BH(5), BL(5));

    float* out = (float*)d_out;
    // ---- update chain t=0 (user) on s0 ----
    gemm128_bf16<<<gg, 256, 0, s0>>>(BH(2), BL(2), WH(8), WL(8), bf_, B(12),
                                     nullptr, nullptr, NN, 1, nullptr, nullptr);  // HZ0
    gemm128_bf16<<<gg, 256, 0, s0>>>(BH(3), BL(3), WH(8), WL(8), bf_, B(13),
                                     nullptr, nullptr, NN, 1, nullptr, nullptr);  // HZ1
    gemm128_bf16<<<gg, 256, 0, s0>>>(BH(6), BL(6), WH(9), WL(9), bx_, B(14),
                                     nullptr, nullptr, NN, 1, nullptr, nullptr);  // XP
    gate_kernel<<<wb, 256, 0, s0>>>(B(12), B(13), B(14), B(8), B(9), BH(8), BL(8));
    gemm128_bf16<<<gg, 256, 0, s0>>>(BH(8), BL(8), WH(10), WL(10), ba_u, out,
                                     nullptr, nullptr, NN, 2, h_user, skip + 0);

    // ---- update chain t=1 (item) on sB ----
    gemm128_bf16<<<gg, 256, 0, sB>>>(BH(4), BL(4), WH(8), WL(8), bf_, B(0),
                                     nullptr, nullptr, NN, 1, nullptr, nullptr);  // HZ0
    gemm128_bf16<<<gg, 256, 0, sB>>>(BH(5), BL(5), WH(8), WL(8), bf_, B(1),
                                     nullptr, nullptr, NN, 1, nullptr, nullptr);  // HZ1
    gemm128_bf16<<<gg, 256, 0, sB>>>(BH(7), BL(7), WH(9), WL(9), bx_, B(2),
                                     nullptr, nullptr, NN, 1, nullptr, nullptr);  // XP
    gate_kernel<<<wb, 256, 0, sB>>>(B(0), B(1), B(2), B(10), B(11), BH(9), BL(9));
    gemm128_bf16<<<gg, 256, 0, sB>>>(BH(9), BL(9), WH(11), WL(11), ba_i,
                                     out + (size_t)NN * CD,
                                     nullptr, nullptr, NN, 2, h_item, skip + 1);

    // ---- final join ----
    cudaEventRecord(ev[5], sB);
    cudaStreamWaitEvent(s0, ev[5], 0);
}